// round 4
// baseline (speedup 1.0000x reference)
#include <cuda_runtime.h>
#include <cuda_bf16.h>
#include <cstdint>

// Problem constants
#define OBS 64
#define ACTD 8
#define DDIM 256
#define SDIM 32
#define HDIM 256
#define BSZ 1024
#define TSTEPS 128
#define TMPN 1280          // D(prior) + D(post-h) + 3D(gru)
#define OUTW 416           // D + 5*S
#define NROWS (BSZ*TSTEPS) // 131072

// ---------------- device scratch ----------------
__device__ float g_h[BSZ * DDIM];                       // fp32 h state
__device__ float g_tmp[BSZ * TMPN];                     // per-step GEMM out
__device__ float g_q1e[(size_t)NROWS * HDIM];           // fp32 posterior emb-side preact
__device__ __nv_bfloat16 g_Ah[BSZ * 768];               // h split [hi|hi|lo]
__device__ __nv_bfloat16 g_Aobs[(size_t)NROWS * 192];   // obs split
__device__ __nv_bfloat16 g_AE1[(size_t)NROWS * 768];    // E1 split
__device__ __nv_bfloat16 g_AE2[(size_t)NROWS * 768];    // E2 split
__device__ __nv_bfloat16 g_Wcat[TMPN * 768];            // [Wp1;Wq1h;Whh] split
__device__ __nv_bfloat16 g_We1p[HDIM * 192];
__device__ __nv_bfloat16 g_We2p[HDIM * 768];
__device__ __nv_bfloat16 g_Wq1ep[HDIM * 768];

// ---------------- split helpers ----------------
__device__ __forceinline__ void split_bf16(float x, __nv_bfloat16& hi, __nv_bfloat16& lo) {
    hi = __float2bfloat16_rn(x);
    lo = __float2bfloat16_rn(x - __bfloat162float(hi));
}

// pack weight fp32 [nrows x K] (row stride srcld) -> bf16 [nrows x 3K] = [hi|lo|hi]
// NOTE layout: A is [hi|hi|lo]; terms are hi*Whi + hi*Wlo + lo*Whi
// so W blocks must be [Whi | Wlo | Whi].
__global__ void pack_split_kernel(const float* __restrict__ src, int srcld,
                                  int nrows, int K, __nv_bfloat16* __restrict__ dst)
{
    int idx = blockIdx.x * blockDim.x + threadIdx.x;
    int total = nrows * K;
    if (idx >= total) return;
    int r = idx / K, k = idx - r * K;
    float w = src[(size_t)r * srcld + k];
    __nv_bfloat16 hi, lo; split_bf16(w, hi, lo);
    __nv_bfloat16* d = dst + (size_t)r * (3 * K);
    d[k] = hi; d[K + k] = lo; d[2 * K + k] = hi;
}

// activation fp32 [rows x K] contiguous -> bf16 [rows x 3K] = [hi|hi|lo]
__global__ void conv_split_kernel(const float* __restrict__ src,
                                  __nv_bfloat16* __restrict__ dst, int K, int total)
{
    int idx = blockIdx.x * blockDim.x + threadIdx.x;
    if (idx >= total) return;
    int r = idx / K, c = idx - r * K;
    float x = src[idx];
    __nv_bfloat16 hi, lo; split_bf16(x, hi, lo);
    __nv_bfloat16* d = dst + (size_t)r * (3 * K);
    d[c] = hi; d[K + c] = hi; d[2 * K + c] = lo;
}

// ---------------- bf16 tensor-core GEMM ----------------
// C[M x N] = act(A[M x K] @ W[N x K]^T + bias), fp32 accumulate.
// A, W: bf16 with row stride K (K = 3*K_logical, multiple of 32).
// Output either fp32 Cf (row stride ldcf) and/or split-bf16 Cs
// (row stride 768, cols [n]=hi, [256+n]=hi, [512+n]=lo; only valid when N<=256).
// BM=64, BN=128, BK=32, 256 threads = 8 warps (2M x 4N), warp tile 32x32.
#define GBM 64
#define GBN 128
#define GBK 32
#define SPAD 40   // padded row stride in bf16 elements (conflict-free frag reads)

__device__ __forceinline__ void mma_bf16(float* c, const uint32_t* a, const uint32_t* b) {
    asm volatile(
        "mma.sync.aligned.m16n8k16.row.col.f32.bf16.bf16.f32 "
        "{%0,%1,%2,%3}, {%4,%5,%6,%7}, {%8,%9}, {%0,%1,%2,%3};\n"
        : "+f"(c[0]), "+f"(c[1]), "+f"(c[2]), "+f"(c[3])
        : "r"(a[0]), "r"(a[1]), "r"(a[2]), "r"(a[3]), "r"(b[0]), "r"(b[1]));
}

__global__ __launch_bounds__(256) void gemm_bf16_kernel(
    const __nv_bfloat16* __restrict__ A,
    const __nv_bfloat16* __restrict__ W,
    const float* __restrict__ bias,
    float* __restrict__ Cf, int ldcf,
    __nv_bfloat16* __restrict__ Cs,
    int K, int actmode)
{
    __shared__ __nv_bfloat16 As[2][GBM][SPAD];
    __shared__ __nv_bfloat16 Ws[2][GBN][SPAD];

    const int tid = threadIdx.x;
    const int lane = tid & 31;
    const int warp = tid >> 5;
    const int wm = warp & 1;        // 2 warps in M
    const int wn = warp >> 1;       // 4 warps in N
    const int gid = lane >> 2;      // 0..7
    const int tg = lane & 3;        // 0..3
    const int m0 = blockIdx.y * GBM;
    const int n0 = blockIdx.x * GBN;

    // loaders
    const int aRow = tid >> 2;            // 0..63
    const int aCol = (tid & 3) * 8;       // 0,8,16,24 (elements)
    const __nv_bfloat16* Ag  = A + (size_t)(m0 + aRow) * K + aCol;
    const __nv_bfloat16* Wg0 = W + (size_t)(n0 + aRow) * K + aCol;
    const __nv_bfloat16* Wg1 = W + (size_t)(n0 + aRow + 64) * K + aCol;

    float acc[2][4][4];
#pragma unroll
    for (int i = 0; i < 2; i++)
#pragma unroll
        for (int j = 0; j < 4; j++)
#pragma unroll
            for (int q = 0; q < 4; q++) acc[i][j][q] = 0.f;

    const int nk = K / GBK;

    // prologue: load tile 0 into stage 0
    uint4 av  = *(const uint4*)(Ag);
    uint4 wv0 = *(const uint4*)(Wg0);
    uint4 wv1 = *(const uint4*)(Wg1);
    *(uint4*)(&As[0][aRow][aCol])      = av;
    *(uint4*)(&Ws[0][aRow][aCol])      = wv0;
    *(uint4*)(&Ws[0][aRow + 64][aCol]) = wv1;
    __syncthreads();

    for (int kb = 0; kb < nk; kb++) {
        const int cur = kb & 1;
        const bool more = (kb + 1 < nk);
        if (more) {
            const int ko = (kb + 1) * GBK;
            av  = *(const uint4*)(Ag + ko);
            wv0 = *(const uint4*)(Wg0 + ko);
            wv1 = *(const uint4*)(Wg1 + ko);
        }
        // compute on stage cur
#pragma unroll
        for (int ks = 0; ks < 2; ks++) {
            const int k0 = ks * 16;
            uint32_t af[2][4];
#pragma unroll
            for (int mf = 0; mf < 2; mf++) {
                const int r = wm * 32 + mf * 16 + gid;
                af[mf][0] = *(const uint32_t*)(&As[cur][r][k0 + tg * 2]);
                af[mf][1] = *(const uint32_t*)(&As[cur][r + 8][k0 + tg * 2]);
                af[mf][2] = *(const uint32_t*)(&As[cur][r][k0 + tg * 2 + 8]);
                af[mf][3] = *(const uint32_t*)(&As[cur][r + 8][k0 + tg * 2 + 8]);
            }
            uint32_t bfr[4][2];
#pragma unroll
            for (int nf = 0; nf < 4; nf++) {
                const int c = wn * 32 + nf * 8 + gid;
                bfr[nf][0] = *(const uint32_t*)(&Ws[cur][c][k0 + tg * 2]);
                bfr[nf][1] = *(const uint32_t*)(&Ws[cur][c][k0 + tg * 2 + 8]);
            }
#pragma unroll
            for (int mf = 0; mf < 2; mf++)
#pragma unroll
                for (int nf = 0; nf < 4; nf++)
                    mma_bf16(acc[mf][nf], af[mf], bfr[nf]);
        }
        if (more) {
            const int nxt = cur ^ 1;
            *(uint4*)(&As[nxt][aRow][aCol])      = av;
            *(uint4*)(&Ws[nxt][aRow][aCol])      = wv0;
            *(uint4*)(&Ws[nxt][aRow + 64][aCol]) = wv1;
        }
        __syncthreads();
    }

    // epilogue
#pragma unroll
    for (int mf = 0; mf < 2; mf++) {
#pragma unroll
        for (int nf = 0; nf < 4; nf++) {
            const int row = m0 + wm * 32 + mf * 16 + gid;
            const int col = n0 + wn * 32 + nf * 8 + tg * 2;
            float v0 = acc[mf][nf][0], v1 = acc[mf][nf][1];
            float v2 = acc[mf][nf][2], v3 = acc[mf][nf][3];
            if (bias) {
                float b0 = bias[col], b1 = bias[col + 1];
                v0 += b0; v1 += b1; v2 += b0; v3 += b1;
            }
            if (actmode == 1) {
                v0 = v0 > 0.f ? v0 : expm1f(v0);
                v1 = v1 > 0.f ? v1 : expm1f(v1);
                v2 = v2 > 0.f ? v2 : expm1f(v2);
                v3 = v3 > 0.f ? v3 : expm1f(v3);
            }
            if (Cf) {
                *(float2*)(Cf + (size_t)row * ldcf + col)       = make_float2(v0, v1);
                *(float2*)(Cf + (size_t)(row + 8) * ldcf + col) = make_float2(v2, v3);
            }
            if (Cs) {
                __nv_bfloat16 h0, l0, h1, l1, h2, l2, h3, l3;
                split_bf16(v0, h0, l0); split_bf16(v1, h1, l1);
                split_bf16(v2, h2, l2); split_bf16(v3, h3, l3);
                __nv_bfloat16* d0 = Cs + (size_t)row * 768 + col;
                __nv_bfloat16* d1 = Cs + (size_t)(row + 8) * 768 + col;
                *(__nv_bfloat162*)(d0)       = __nv_bfloat162(h0, h1);
                *(__nv_bfloat162*)(d0 + 256) = __nv_bfloat162(h0, h1);
                *(__nv_bfloat162*)(d0 + 512) = __nv_bfloat162(l0, l1);
                *(__nv_bfloat162*)(d1)       = __nv_bfloat162(h2, h3);
                *(__nv_bfloat162*)(d1 + 256) = __nv_bfloat162(h2, h3);
                *(__nv_bfloat162*)(d1 + 512) = __nv_bfloat162(l2, l3);
            }
        }
    }
}

// ---------------- fused per-step kernel ----------------
#define RPB 8

__device__ __forceinline__ float sigmf(float x) { return 1.f / (1.f + expf(-x)); }

__global__ __launch_bounds__(256) void step_kernel(
    int t,
    const float* __restrict__ q1e,     // [B*T, 256]
    const float* __restrict__ noise,   // [T, B, S]
    const float* __restrict__ act,     // [B, T, ACT]
    const float* __restrict__ Wp2, const float* __restrict__ bp2,
    const float* __restrict__ Wq2, const float* __restrict__ bq2,
    const float* __restrict__ bp1,
    const float* __restrict__ Wih, const float* __restrict__ bih,
    const float* __restrict__ bhh,
    float* __restrict__ out)           // [B, T, 416]
{
    __shared__ float PQ[2][RPB][256];
    __shared__ float ST[RPB][128];     // pstats(64) | qstats(64)
    __shared__ float ZA[RPB][40];      // z(32) | act(8)

    const int tid = threadIdx.x;
    const int b0 = blockIdx.x * RPB;

    // ---- stage 1: load tmp, add biases, ELU ----
    for (int i = tid; i < RPB * 256; i += 256) {
        int r = i >> 8, d = i & 255;
        int b = b0 + r;
        const float* trow = g_tmp + (size_t)b * TMPN;
        float p = trow[d] + bp1[d];
        PQ[0][r][d] = p > 0.f ? p : expm1f(p);
        float q = trow[256 + d] + q1e[((size_t)b * TSTEPS + t) * 256 + d];
        PQ[1][r][d] = q > 0.f ? q : expm1f(q);
    }
    __syncthreads();

    // ---- stage 2: prior/posterior stats ----
    {
        int j = tid & 127;
        int rbase = tid >> 7;
        bool isq = (j >= 64);
        int jj = isq ? j - 64 : j;
        const float* wrow = (isq ? Wq2 : Wp2) + jj * 256;
        float bb = (isq ? bq2 : bp2)[jj];
        const float* base = &PQ[isq ? 1 : 0][0][0];

        float accm[4] = {0.f, 0.f, 0.f, 0.f};
        for (int k = 0; k < 256; k += 4) {
            float4 w = *(const float4*)(wrow + k);
#pragma unroll
            for (int m = 0; m < 4; m++) {
                int r = rbase + 2 * m;
                float4 s = *(const float4*)(base + r * 256 + k);
                accm[m] += s.x * w.x + s.y * w.y + s.z * w.z + s.w * w.w;
            }
        }
#pragma unroll
        for (int m = 0; m < 4; m++) ST[rbase + 2 * m][j] = accm[m] + bb;
    }
    __syncthreads();

    // ---- stage 3: z = qm + qs*eps ; stage act ----
    {
        int r = tid >> 5, s = tid & 31;
        int b = b0 + r;
        float qm = ST[r][64 + s];
        float ql = fminf(fmaxf(ST[r][96 + s], -7.f), 5.f);
        float qs = expf(ql);
        float eps = noise[((size_t)t * BSZ + b) * SDIM + s];
        ZA[r][s] = qm + qs * eps;
    }
    if (tid < RPB * ACTD) {
        int r = tid >> 3, j = tid & 7;
        int b = b0 + r;
        ZA[r][32 + j] = act[((size_t)b * TSTEPS + t) * ACTD + j];
    }
    __syncthreads();

    // ---- stage 4: GRU gates + h update + write h_old + split-bf16 h_new ----
#pragma unroll 1
    for (int r = 0; r < RPB; r++) {
        int d = tid;
        int b = b0 + r;
        float gi[3];
#pragma unroll
        for (int g = 0; g < 3; g++) {
            const float* w = Wih + (size_t)(g * 256 + d) * 40;
            float a = 0.f;
#pragma unroll
            for (int k4 = 0; k4 < 10; k4++) {
                float4 wv = *(const float4*)(w + 4 * k4);
                float4 sv = *(const float4*)(&ZA[r][4 * k4]);
                a += sv.x * wv.x + sv.y * wv.y + sv.z * wv.z + sv.w * wv.w;
            }
            gi[g] = a + bih[g * 256 + d];
        }
        const float* trow = g_tmp + (size_t)b * TMPN + 512;
        float ghr = trow[d]        + bhh[d];
        float ghu = trow[256 + d]  + bhh[256 + d];
        float ghn = trow[512 + d]  + bhh[512 + d];
        float rg = sigmf(gi[0] + ghr);
        float u  = sigmf(gi[1] + ghu);
        float nn = tanhf(gi[2] + rg * ghn);
        float hold = g_h[(size_t)b * DDIM + d];
        float hnew = (1.f - u) * nn + u * hold;
        out[((size_t)b * TSTEPS + t) * OUTW + d] = hold;
        g_h[(size_t)b * DDIM + d] = hnew;
        __nv_bfloat16 hi, lo; split_bf16(hnew, hi, lo);
        __nv_bfloat16* arow = g_Ah + (size_t)b * 768;
        arow[d] = hi; arow[256 + d] = hi; arow[512 + d] = lo;
    }

    // ---- stage 5: write z, pm, ps, qm, qs ----
    for (int i = tid; i < RPB * 160; i += 256) {
        int r = i / 160, c = i - r * 160;
        int b = b0 + r;
        float v;
        if (c < 32) {
            v = ZA[r][c];
        } else {
            v = ST[r][c - 32];
            if ((c >= 64 && c < 96) || c >= 128) {
                v = expf(fminf(fmaxf(v, -7.f), 5.f));
            }
        }
        out[((size_t)b * TSTEPS + t) * OUTW + 256 + c] = v;
    }
}

// ---------------- host launch ----------------
extern "C" void kernel_launch(void* const* d_in, const int* in_sizes, int n_in,
                              void* d_out, int out_size)
{
    (void)in_sizes; (void)n_in; (void)out_size;
    const float* obs  = (const float*)d_in[0];
    const float* actp = (const float*)d_in[1];
    const float* noi  = (const float*)d_in[2];
    const float* We1  = (const float*)d_in[3];
    const float* be1  = (const float*)d_in[4];
    const float* We2  = (const float*)d_in[5];
    const float* be2  = (const float*)d_in[6];
    const float* Wih  = (const float*)d_in[7];
    const float* Whh  = (const float*)d_in[8];
    const float* bih  = (const float*)d_in[9];
    const float* bhh  = (const float*)d_in[10];
    const float* Wp1  = (const float*)d_in[11];
    const float* bp1  = (const float*)d_in[12];
    const float* Wp2  = (const float*)d_in[13];
    const float* bp2  = (const float*)d_in[14];
    const float* Wq1  = (const float*)d_in[15];
    const float* bq1  = (const float*)d_in[16];
    const float* Wq2  = (const float*)d_in[17];
    const float* bq2  = (const float*)d_in[18];
    float* out = (float*)d_out;

    float *p_h, *p_tmp, *p_q1e;
    __nv_bfloat16 *p_Ah, *p_Aobs, *p_AE1, *p_AE2, *p_Wcat, *p_We1p, *p_We2p, *p_Wq1ep;
    cudaGetSymbolAddress((void**)&p_h,     g_h);
    cudaGetSymbolAddress((void**)&p_tmp,   g_tmp);
    cudaGetSymbolAddress((void**)&p_q1e,   g_q1e);
    cudaGetSymbolAddress((void**)&p_Ah,    g_Ah);
    cudaGetSymbolAddress((void**)&p_Aobs,  g_Aobs);
    cudaGetSymbolAddress((void**)&p_AE1,   g_AE1);
    cudaGetSymbolAddress((void**)&p_AE2,   g_AE2);
    cudaGetSymbolAddress((void**)&p_Wcat,  g_Wcat);
    cudaGetSymbolAddress((void**)&p_We1p,  g_We1p);
    cudaGetSymbolAddress((void**)&p_We2p,  g_We2p);
    cudaGetSymbolAddress((void**)&p_Wq1ep, g_Wq1ep);

    cudaMemsetAsync(p_h, 0, sizeof(float) * BSZ * DDIM, 0);
    cudaMemsetAsync(p_Ah, 0, sizeof(__nv_bfloat16) * BSZ * 768, 0);

    // ---- pack weights (split bf16) ----
    {
        auto blocks = [](int n) { return (n + 255) / 256; };
        pack_split_kernel<<<blocks(256 * 256), 256>>>(Wp1, 256, 256, 256, p_Wcat);
        pack_split_kernel<<<blocks(256 * 256), 256>>>(Wq1, 512, 256, 256, p_Wcat + (size_t)256 * 768);
        pack_split_kernel<<<blocks(768 * 256), 256>>>(Whh, 256, 768, 256, p_Wcat + (size_t)512 * 768);
        pack_split_kernel<<<blocks(256 * 64),  256>>>(We1, 64,  256, 64,  p_We1p);
        pack_split_kernel<<<blocks(256 * 256), 256>>>(We2, 256, 256, 256, p_We2p);
        pack_split_kernel<<<blocks(256 * 256), 256>>>(Wq1 + 256, 512, 256, 256, p_Wq1ep);
    }

    // ---- obs -> split bf16 ----
    conv_split_kernel<<<(NROWS * OBS + 255) / 256, 256>>>(obs, p_Aobs, OBS, NROWS * OBS);

    // ---- precompute: E1 = elu(obs@We1^T+be1) ; E2 = elu(E1@We2^T+be2) ;
    //                  q1e = E2@Wq1[:,D:]^T + bq1 ----
    {
        dim3 g1(HDIM / GBN, NROWS / GBM);   // (2, 2048)
        gemm_bf16_kernel<<<g1, 256>>>(p_Aobs, p_We1p, be1, nullptr, 0, p_AE1, 192, 1);
        gemm_bf16_kernel<<<g1, 256>>>(p_AE1, p_We2p, be2, nullptr, 0, p_AE2, 768, 1);
        gemm_bf16_kernel<<<g1, 256>>>(p_AE2, p_Wq1ep, bq1, p_q1e, HDIM, nullptr, 768, 0);
    }

    // ---- sequential scan ----
    dim3 gk1(TMPN / GBN, BSZ / GBM);   // (10, 16) = 160 blocks
    for (int t = 0; t < TSTEPS; t++) {
        gemm_bf16_kernel<<<gk1, 256>>>(p_Ah, p_Wcat, nullptr, p_tmp, TMPN, nullptr, 768, 0);
        step_kernel<<<BSZ / RPB, 256>>>(t, p_q1e, noi, actp,
                                        Wp2, bp2, Wq2, bq2, bp1,
                                        Wih, bih, bhh, out);
    }
}

// round 5
// speedup vs baseline: 1.6382x; 1.6382x over previous
#include <cuda_runtime.h>
#include <cuda_bf16.h>
#include <cstdint>

// Problem constants
#define OBS 64
#define ACTD 8
#define DDIM 256
#define SDIM 32
#define HDIM 256
#define BSZ 1024
#define TSTEPS 128
#define TMPN 1280          // D(prior) + D(post-h) + 3D(gru)
#define OUTW 416           // D + 5*S
#define NROWS (BSZ*TSTEPS) // 131072

// ---------------- device scratch ----------------
__device__ float g_h[BSZ * DDIM];                       // fp32 h state
__device__ float g_tmp[BSZ * TMPN];                     // per-step GEMM out
__device__ float g_q1e[(size_t)NROWS * HDIM];           // fp32 posterior emb-side preact
__device__ __nv_bfloat16 g_Ah[BSZ * 768];               // h split [hi|hi|lo]
__device__ __nv_bfloat16 g_Aobs[(size_t)NROWS * 192];   // obs split
__device__ __nv_bfloat16 g_AE1[(size_t)NROWS * 768];    // E1 split
__device__ __nv_bfloat16 g_AE2[(size_t)NROWS * 768];    // E2 split
__device__ __nv_bfloat16 g_Wcat[TMPN * 768];            // [Wp1;Wq1h;Whh] split
__device__ __nv_bfloat16 g_We1p[HDIM * 192];
__device__ __nv_bfloat16 g_We2p[HDIM * 768];
__device__ __nv_bfloat16 g_Wq1ep[HDIM * 768];

// grid barrier state
__device__ unsigned g_bar_count = 0;
__device__ volatile unsigned g_bar_gen = 0;

// ---------------- split helpers ----------------
__device__ __forceinline__ void split_bf16(float x, __nv_bfloat16& hi, __nv_bfloat16& lo) {
    hi = __float2bfloat16_rn(x);
    lo = __float2bfloat16_rn(x - __bfloat162float(hi));
}

// pack weight fp32 [nrows x K] (row stride srcld) -> bf16 [nrows x 3K] = [Whi|Wlo|Whi]
__global__ void pack_split_kernel(const float* __restrict__ src, int srcld,
                                  int nrows, int K, __nv_bfloat16* __restrict__ dst)
{
    int idx = blockIdx.x * blockDim.x + threadIdx.x;
    int total = nrows * K;
    if (idx >= total) return;
    int r = idx / K, k = idx - r * K;
    float w = src[(size_t)r * srcld + k];
    __nv_bfloat16 hi, lo; split_bf16(w, hi, lo);
    __nv_bfloat16* d = dst + (size_t)r * (3 * K);
    d[k] = hi; d[K + k] = lo; d[2 * K + k] = hi;
}

// activation fp32 [rows x K] contiguous -> bf16 [rows x 3K] = [hi|hi|lo]
__global__ void conv_split_kernel(const float* __restrict__ src,
                                  __nv_bfloat16* __restrict__ dst, int K, int total)
{
    int idx = blockIdx.x * blockDim.x + threadIdx.x;
    if (idx >= total) return;
    int r = idx / K, c = idx - r * K;
    float x = src[idx];
    __nv_bfloat16 hi, lo; split_bf16(x, hi, lo);
    __nv_bfloat16* d = dst + (size_t)r * (3 * K);
    d[c] = hi; d[K + c] = hi; d[2 * K + c] = lo;
}

// ---------------- bf16 tensor-core GEMM (precompute only) ----------------
#define GBM 64
#define GBN 128
#define GBK 32
#define SPAD 40

__device__ __forceinline__ void mma_bf16(float* c, const uint32_t* a, const uint32_t* b) {
    asm volatile(
        "mma.sync.aligned.m16n8k16.row.col.f32.bf16.bf16.f32 "
        "{%0,%1,%2,%3}, {%4,%5,%6,%7}, {%8,%9}, {%0,%1,%2,%3};\n"
        : "+f"(c[0]), "+f"(c[1]), "+f"(c[2]), "+f"(c[3])
        : "r"(a[0]), "r"(a[1]), "r"(a[2]), "r"(a[3]), "r"(b[0]), "r"(b[1]));
}

__global__ __launch_bounds__(256) void gemm_bf16_kernel(
    const __nv_bfloat16* __restrict__ A,
    const __nv_bfloat16* __restrict__ W,
    const float* __restrict__ bias,
    float* __restrict__ Cf, int ldcf,
    __nv_bfloat16* __restrict__ Cs,
    int K, int actmode)
{
    __shared__ __nv_bfloat16 As[2][GBM][SPAD];
    __shared__ __nv_bfloat16 Ws[2][GBN][SPAD];

    const int tid = threadIdx.x;
    const int lane = tid & 31;
    const int warp = tid >> 5;
    const int wm = warp & 1;
    const int wn = warp >> 1;
    const int gid = lane >> 2;
    const int tg = lane & 3;
    const int m0 = blockIdx.y * GBM;
    const int n0 = blockIdx.x * GBN;

    const int aRow = tid >> 2;
    const int aCol = (tid & 3) * 8;
    const __nv_bfloat16* Ag  = A + (size_t)(m0 + aRow) * K + aCol;
    const __nv_bfloat16* Wg0 = W + (size_t)(n0 + aRow) * K + aCol;
    const __nv_bfloat16* Wg1 = W + (size_t)(n0 + aRow + 64) * K + aCol;

    float acc[2][4][4];
#pragma unroll
    for (int i = 0; i < 2; i++)
#pragma unroll
        for (int j = 0; j < 4; j++)
#pragma unroll
            for (int q = 0; q < 4; q++) acc[i][j][q] = 0.f;

    const int nk = K / GBK;

    uint4 av  = *(const uint4*)(Ag);
    uint4 wv0 = *(const uint4*)(Wg0);
    uint4 wv1 = *(const uint4*)(Wg1);
    *(uint4*)(&As[0][aRow][aCol])      = av;
    *(uint4*)(&Ws[0][aRow][aCol])      = wv0;
    *(uint4*)(&Ws[0][aRow + 64][aCol]) = wv1;
    __syncthreads();

    for (int kb = 0; kb < nk; kb++) {
        const int cur = kb & 1;
        const bool more = (kb + 1 < nk);
        if (more) {
            const int ko = (kb + 1) * GBK;
            av  = *(const uint4*)(Ag + ko);
            wv0 = *(const uint4*)(Wg0 + ko);
            wv1 = *(const uint4*)(Wg1 + ko);
        }
#pragma unroll
        for (int ks = 0; ks < 2; ks++) {
            const int k0 = ks * 16;
            uint32_t af[2][4];
#pragma unroll
            for (int mf = 0; mf < 2; mf++) {
                const int r = wm * 32 + mf * 16 + gid;
                af[mf][0] = *(const uint32_t*)(&As[cur][r][k0 + tg * 2]);
                af[mf][1] = *(const uint32_t*)(&As[cur][r + 8][k0 + tg * 2]);
                af[mf][2] = *(const uint32_t*)(&As[cur][r][k0 + tg * 2 + 8]);
                af[mf][3] = *(const uint32_t*)(&As[cur][r + 8][k0 + tg * 2 + 8]);
            }
            uint32_t bfr[4][2];
#pragma unroll
            for (int nf = 0; nf < 4; nf++) {
                const int c = wn * 32 + nf * 8 + gid;
                bfr[nf][0] = *(const uint32_t*)(&Ws[cur][c][k0 + tg * 2]);
                bfr[nf][1] = *(const uint32_t*)(&Ws[cur][c][k0 + tg * 2 + 8]);
            }
#pragma unroll
            for (int mf = 0; mf < 2; mf++)
#pragma unroll
                for (int nf = 0; nf < 4; nf++)
                    mma_bf16(acc[mf][nf], af[mf], bfr[nf]);
        }
        if (more) {
            const int nxt = cur ^ 1;
            *(uint4*)(&As[nxt][aRow][aCol])      = av;
            *(uint4*)(&Ws[nxt][aRow][aCol])      = wv0;
            *(uint4*)(&Ws[nxt][aRow + 64][aCol]) = wv1;
        }
        __syncthreads();
    }

#pragma unroll
    for (int mf = 0; mf < 2; mf++) {
#pragma unroll
        for (int nf = 0; nf < 4; nf++) {
            const int row = m0 + wm * 32 + mf * 16 + gid;
            const int col = n0 + wn * 32 + nf * 8 + tg * 2;
            float v0 = acc[mf][nf][0], v1 = acc[mf][nf][1];
            float v2 = acc[mf][nf][2], v3 = acc[mf][nf][3];
            if (bias) {
                float b0 = bias[col], b1 = bias[col + 1];
                v0 += b0; v1 += b1; v2 += b0; v3 += b1;
            }
            if (actmode == 1) {
                v0 = v0 > 0.f ? v0 : expm1f(v0);
                v1 = v1 > 0.f ? v1 : expm1f(v1);
                v2 = v2 > 0.f ? v2 : expm1f(v2);
                v3 = v3 > 0.f ? v3 : expm1f(v3);
            }
            if (Cf) {
                *(float2*)(Cf + (size_t)row * ldcf + col)       = make_float2(v0, v1);
                *(float2*)(Cf + (size_t)(row + 8) * ldcf + col) = make_float2(v2, v3);
            }
            if (Cs) {
                __nv_bfloat16 h0, l0, h1, l1, h2, l2, h3, l3;
                split_bf16(v0, h0, l0); split_bf16(v1, h1, l1);
                split_bf16(v2, h2, l2); split_bf16(v3, h3, l3);
                __nv_bfloat16* d0 = Cs + (size_t)row * 768 + col;
                __nv_bfloat16* d1 = Cs + (size_t)(row + 8) * 768 + col;
                *(__nv_bfloat162*)(d0)       = __nv_bfloat162(h0, h1);
                *(__nv_bfloat162*)(d0 + 256) = __nv_bfloat162(h0, h1);
                *(__nv_bfloat162*)(d0 + 512) = __nv_bfloat162(l0, l1);
                *(__nv_bfloat162*)(d1)       = __nv_bfloat162(h2, h3);
                *(__nv_bfloat162*)(d1 + 256) = __nv_bfloat162(h2, h3);
                *(__nv_bfloat162*)(d1 + 512) = __nv_bfloat162(l2, l3);
            }
        }
    }
}

// ================= persistent scan kernel =================
// grid = 128 blocks x 256 threads, all co-resident (1 block/SM).
// Each block: GEMM tile = batch strip (bs = blk>>4, 128 rows) x col slice
// (cs = blk&15, 80 of 1280 cols), W slice (80x768 bf16) persistent in smem.
// Step phase: 8 batch rows per block (b0 = blk*8).
#define NBLK 128
#define WSLICE 80          // cols per block of TMPN
#define WPAD 776           // 768 + 8 pad (bank decorrelation)
#define KTILES 48          // 768 / 16

// dynamic smem layout (bytes)
#define SM_W    0
#define SM_AS   (WSLICE * WPAD * 2)                    // 124160
#define SM_PQ   (SM_AS + 2 * 128 * 24 * 2)             // +12288 = 136448
#define SM_ST   (SM_PQ + 2 * 8 * 256 * 4)              // +16384 = 152832
#define SM_ZA   (SM_ST + 8 * 128 * 4)                  // +4096  = 156928
#define SM_TOTAL (SM_ZA + 8 * 40 * 4)                  // +1280  = 158208

__device__ __forceinline__ float sigmf(float x) { return 1.f / (1.f + expf(-x)); }

__device__ __forceinline__ void grid_sync() {
    __syncthreads();
    if (threadIdx.x == 0) {
        __threadfence();
        unsigned gen = g_bar_gen;
        unsigned arrived = atomicAdd(&g_bar_count, 1u);
        if (arrived == NBLK - 1) {
            g_bar_count = 0;
            __threadfence();
            g_bar_gen = gen + 1;
        } else {
            while (g_bar_gen == gen) { }
        }
        __threadfence();
    }
    __syncthreads();
}

__global__ __launch_bounds__(256, 1) void scan_kernel(
    const float* __restrict__ q1e,     // [B*T, 256]
    const float* __restrict__ noise,   // [T, B, S]
    const float* __restrict__ act,     // [B, T, ACT]
    const float* __restrict__ Wp2, const float* __restrict__ bp2,
    const float* __restrict__ Wq2, const float* __restrict__ bq2,
    const float* __restrict__ bp1,
    const float* __restrict__ Wih, const float* __restrict__ bih,
    const float* __restrict__ bhh,
    float* __restrict__ out)           // [B, T, 416]
{
    extern __shared__ char smraw[];
    __nv_bfloat16* Wsm = (__nv_bfloat16*)(smraw + SM_W);    // [80][776]
    __nv_bfloat16* As  = (__nv_bfloat16*)(smraw + SM_AS);   // [2][128][24]
    float* PQ = (float*)(smraw + SM_PQ);                    // [2][8][256]
    float* ST = (float*)(smraw + SM_ST);                    // [8][128]
    float* ZA = (float*)(smraw + SM_ZA);                    // [8][40]

    const int tid = threadIdx.x;
    const int blk = blockIdx.x;
    const int lane = tid & 31;
    const int warp = tid >> 5;
    const int gid = lane >> 2;
    const int tg = lane & 3;
    const int wm = warp & 3;         // 4 M-warps
    const int wn = warp >> 2;        // 2 N-warps
    const int bs = blk >> 4;         // batch strip 0..7 (128 rows)
    const int cs = blk & 15;         // col slice 0..15 (80 cols)
    const int mbase = bs * 128;
    const int nbase = cs * WSLICE;
    const int b0 = blk * 8;          // step-phase rows

    // ---- load W slice into smem (once) ----
    for (int i = tid; i < WSLICE * 768; i += 256) {
        int r = i / 768, k = i - r * 768;
        Wsm[r * WPAD + k] = g_Wcat[(size_t)(nbase + r) * 768 + k];
    }
    __syncthreads();

    const int lrow = tid >> 1;            // 0..127
    const int kcol = (tid & 1) * 8;       // 0 or 8

    for (int t = 0; t < TSTEPS; t++) {
        // ======== phase G: tmp[strip][slice] = h_split @ Wslice^T ========
        {
            float acc[2][5][4];
#pragma unroll
            for (int i = 0; i < 2; i++)
#pragma unroll
                for (int j = 0; j < 5; j++)
#pragma unroll
                    for (int q = 0; q < 4; q++) acc[i][j][q] = 0.f;

            uint4 av = *(const uint4*)(&g_Ah[(size_t)(mbase + lrow) * 768 + kcol]);
            *(uint4*)(&As[(0 * 128 + lrow) * 24 + kcol]) = av;
            __syncthreads();

            for (int kb = 0; kb < KTILES; kb++) {
                const int cur = kb & 1;
                const bool more = (kb + 1 < KTILES);
                if (more)
                    av = *(const uint4*)(&g_Ah[(size_t)(mbase + lrow) * 768 + (kb + 1) * 16 + kcol]);

                uint32_t af[2][4];
#pragma unroll
                for (int mf = 0; mf < 2; mf++) {
                    const int r = wm * 32 + mf * 16 + gid;
                    const __nv_bfloat16* arow = &As[(cur * 128 + r) * 24];
                    af[mf][0] = *(const uint32_t*)(arow + tg * 2);
                    af[mf][1] = *(const uint32_t*)(arow + 24 * 8 + tg * 2);
                    af[mf][2] = *(const uint32_t*)(arow + tg * 2 + 8);
                    af[mf][3] = *(const uint32_t*)(arow + 24 * 8 + tg * 2 + 8);
                }
                uint32_t bfr[5][2];
#pragma unroll
                for (int nf = 0; nf < 5; nf++) {
                    const int c = wn * 40 + nf * 8 + gid;
                    const __nv_bfloat16* wrow = &Wsm[c * WPAD + kb * 16];
                    bfr[nf][0] = *(const uint32_t*)(wrow + tg * 2);
                    bfr[nf][1] = *(const uint32_t*)(wrow + tg * 2 + 8);
                }
#pragma unroll
                for (int mf = 0; mf < 2; mf++)
#pragma unroll
                    for (int nf = 0; nf < 5; nf++)
                        mma_bf16(acc[mf][nf], af[mf], bfr[nf]);

                if (more)
                    *(uint4*)(&As[((cur ^ 1) * 128 + lrow) * 24 + kcol]) = av;
                __syncthreads();
            }

#pragma unroll
            for (int mf = 0; mf < 2; mf++)
#pragma unroll
                for (int nf = 0; nf < 5; nf++) {
                    const int row = mbase + wm * 32 + mf * 16 + gid;
                    const int col = nbase + wn * 40 + nf * 8 + tg * 2;
                    *(float2*)(&g_tmp[(size_t)row * TMPN + col]) =
                        make_float2(acc[mf][nf][0], acc[mf][nf][1]);
                    *(float2*)(&g_tmp[(size_t)(row + 8) * TMPN + col]) =
                        make_float2(acc[mf][nf][2], acc[mf][nf][3]);
                }
        }
        grid_sync();

        // ======== phase S: elementwise step for rows b0..b0+7 ========
        // stage 1: biases + ELU
        for (int i = tid; i < 8 * 256; i += 256) {
            int r = i >> 8, d = i & 255;
            int b = b0 + r;
            const float* trow = g_tmp + (size_t)b * TMPN;
            float p = trow[d] + bp1[d];
            PQ[(0 * 8 + r) * 256 + d] = p > 0.f ? p : expm1f(p);
            float q = trow[256 + d] + q1e[((size_t)b * TSTEPS + t) * 256 + d];
            PQ[(1 * 8 + r) * 256 + d] = q > 0.f ? q : expm1f(q);
        }
        __syncthreads();

        // stage 2: prior/posterior stats
        {
            int j = tid & 127;
            int rbase = tid >> 7;
            bool isq = (j >= 64);
            int jj = isq ? j - 64 : j;
            const float* wrow = (isq ? Wq2 : Wp2) + jj * 256;
            float bb = (isq ? bq2 : bp2)[jj];
            const float* base = PQ + (isq ? 8 * 256 : 0);

            float accm[4] = {0.f, 0.f, 0.f, 0.f};
            for (int k = 0; k < 256; k += 4) {
                float4 w = *(const float4*)(wrow + k);
#pragma unroll
                for (int m = 0; m < 4; m++) {
                    int r = rbase + 2 * m;
                    float4 s = *(const float4*)(base + r * 256 + k);
                    accm[m] += s.x * w.x + s.y * w.y + s.z * w.z + s.w * w.w;
                }
            }
#pragma unroll
            for (int m = 0; m < 4; m++) ST[(rbase + 2 * m) * 128 + j] = accm[m] + bb;
        }
        __syncthreads();

        // stage 3: z = qm + qs*eps ; stage act
        {
            int r = tid >> 5, s = tid & 31;
            int b = b0 + r;
            float qm = ST[r * 128 + 64 + s];
            float ql = fminf(fmaxf(ST[r * 128 + 96 + s], -7.f), 5.f);
            float qs = expf(ql);
            float eps = noise[((size_t)t * BSZ + b) * SDIM + s];
            ZA[r * 40 + s] = qm + qs * eps;
        }
        if (tid < 8 * ACTD) {
            int r = tid >> 3, j = tid & 7;
            int b = b0 + r;
            ZA[r * 40 + 32 + j] = act[((size_t)b * TSTEPS + t) * ACTD + j];
        }
        __syncthreads();

        // stage 4: GRU gates + h update + write h_old + split h_new
#pragma unroll 1
        for (int r = 0; r < 8; r++) {
            int d = tid;
            int b = b0 + r;
            float gi[3];
#pragma unroll
            for (int g = 0; g < 3; g++) {
                const float* w = Wih + (size_t)(g * 256 + d) * 40;
                float a = 0.f;
#pragma unroll
                for (int k4 = 0; k4 < 10; k4++) {
                    float4 wv = *(const float4*)(w + 4 * k4);
                    float4 sv = *(const float4*)(&ZA[r * 40 + 4 * k4]);
                    a += sv.x * wv.x + sv.y * wv.y + sv.z * wv.z + sv.w * wv.w;
                }
                gi[g] = a + bih[g * 256 + d];
            }
            const float* trow = g_tmp + (size_t)b * TMPN + 512;
            float ghr = trow[d]        + bhh[d];
            float ghu = trow[256 + d]  + bhh[256 + d];
            float ghn = trow[512 + d]  + bhh[512 + d];
            float rg = sigmf(gi[0] + ghr);
            float u  = sigmf(gi[1] + ghu);
            float nn = tanhf(gi[2] + rg * ghn);
            float hold = g_h[(size_t)b * DDIM + d];
            float hnew = (1.f - u) * nn + u * hold;
            out[((size_t)b * TSTEPS + t) * OUTW + d] = hold;
            g_h[(size_t)b * DDIM + d] = hnew;
            __nv_bfloat16 hi, lo; split_bf16(hnew, hi, lo);
            __nv_bfloat16* arow = g_Ah + (size_t)b * 768;
            arow[d] = hi; arow[256 + d] = hi; arow[512 + d] = lo;
        }

        // stage 5: write z, pm, ps, qm, qs
        for (int i = tid; i < 8 * 160; i += 256) {
            int r = i / 160, c = i - r * 160;
            int b = b0 + r;
            float v;
            if (c < 32) {
                v = ZA[r * 40 + c];
            } else {
                v = ST[r * 128 + c - 32];
                if ((c >= 64 && c < 96) || c >= 128) {
                    v = expf(fminf(fmaxf(v, -7.f), 5.f));
                }
            }
            out[((size_t)b * TSTEPS + t) * OUTW + 256 + c] = v;
        }
        grid_sync();
    }
}

// ---------------- host launch ----------------
extern "C" void kernel_launch(void* const* d_in, const int* in_sizes, int n_in,
                              void* d_out, int out_size)
{
    (void)in_sizes; (void)n_in; (void)out_size;
    const float* obs  = (const float*)d_in[0];
    const float* actp = (const float*)d_in[1];
    const float* noi  = (const float*)d_in[2];
    const float* We1  = (const float*)d_in[3];
    const float* be1  = (const float*)d_in[4];
    const float* We2  = (const float*)d_in[5];
    const float* be2  = (const float*)d_in[6];
    const float* Wih  = (const float*)d_in[7];
    const float* Whh  = (const float*)d_in[8];
    const float* bih  = (const float*)d_in[9];
    const float* bhh  = (const float*)d_in[10];
    const float* Wp1  = (const float*)d_in[11];
    const float* bp1  = (const float*)d_in[12];
    const float* Wp2  = (const float*)d_in[13];
    const float* bp2  = (const float*)d_in[14];
    const float* Wq1  = (const float*)d_in[15];
    const float* bq1  = (const float*)d_in[16];
    const float* Wq2  = (const float*)d_in[17];
    const float* bq2  = (const float*)d_in[18];
    float* out = (float*)d_out;

    float *p_h, *p_q1e;
    __nv_bfloat16 *p_Ah, *p_Aobs, *p_AE1, *p_AE2, *p_Wcat, *p_We1p, *p_We2p, *p_Wq1ep;
    cudaGetSymbolAddress((void**)&p_h,     g_h);
    cudaGetSymbolAddress((void**)&p_q1e,   g_q1e);
    cudaGetSymbolAddress((void**)&p_Ah,    g_Ah);
    cudaGetSymbolAddress((void**)&p_Aobs,  g_Aobs);
    cudaGetSymbolAddress((void**)&p_AE1,   g_AE1);
    cudaGetSymbolAddress((void**)&p_AE2,   g_AE2);
    cudaGetSymbolAddress((void**)&p_Wcat,  g_Wcat);
    cudaGetSymbolAddress((void**)&p_We1p,  g_We1p);
    cudaGetSymbolAddress((void**)&p_We2p,  g_We2p);
    cudaGetSymbolAddress((void**)&p_Wq1ep, g_Wq1ep);

    cudaMemsetAsync(p_h, 0, sizeof(float) * BSZ * DDIM, 0);
    cudaMemsetAsync(p_Ah, 0, sizeof(__nv_bfloat16) * BSZ * 768, 0);

    // ---- pack weights (split bf16) ----
    {
        auto blocks = [](int n) { return (n + 255) / 256; };
        pack_split_kernel<<<blocks(256 * 256), 256>>>(Wp1, 256, 256, 256, p_Wcat);
        pack_split_kernel<<<blocks(256 * 256), 256>>>(Wq1, 512, 256, 256, p_Wcat + (size_t)256 * 768);
        pack_split_kernel<<<blocks(768 * 256), 256>>>(Whh, 256, 768, 256, p_Wcat + (size_t)512 * 768);
        pack_split_kernel<<<blocks(256 * 64),  256>>>(We1, 64,  256, 64,  p_We1p);
        pack_split_kernel<<<blocks(256 * 256), 256>>>(We2, 256, 256, 256, p_We2p);
        pack_split_kernel<<<blocks(256 * 256), 256>>>(Wq1 + 256, 512, 256, 256, p_Wq1ep);
    }

    // ---- obs -> split bf16 ----
    conv_split_kernel<<<(NROWS * OBS + 255) / 256, 256>>>(obs, p_Aobs, OBS, NROWS * OBS);

    // ---- precompute: E1, E2, q1e ----
    {
        dim3 g1(HDIM / GBN, NROWS / GBM);   // (2, 2048)
        gemm_bf16_kernel<<<g1, 256>>>(p_Aobs, p_We1p, be1, nullptr, 0, p_AE1, 192, 1);
        gemm_bf16_kernel<<<g1, 256>>>(p_AE1, p_We2p, be2, nullptr, 0, p_AE2, 768, 1);
        gemm_bf16_kernel<<<g1, 256>>>(p_AE2, p_Wq1ep, bq1, p_q1e, HDIM, nullptr, 768, 0);
    }

    // ---- persistent scan ----
    static bool attr_set = false;
    if (!attr_set) {
        cudaFuncSetAttribute(scan_kernel,
                             cudaFuncAttributeMaxDynamicSharedMemorySize, SM_TOTAL);
        attr_set = true;
    }
    scan_kernel<<<NBLK, 256, SM_TOTAL>>>(p_q1e, noi, actp,
                                         Wp2, bp2, Wq2, bq2, bp1,
                                         Wih, bih, bhh, out);
}

// round 7
// speedup vs baseline: 1.6690x; 1.0188x over previous
#include <cuda_runtime.h>
#include <cuda_bf16.h>
#include <cstdint>

// Problem constants
#define OBS 64
#define ACTD 8
#define DDIM 256
#define SDIM 32
#define HDIM 256
#define BSZ 1024
#define TSTEPS 128
#define TMPN 1280          // D(prior) + D(post-h) + 3D(gru)
#define OUTW 416           // D + 5*S
#define NROWS (BSZ*TSTEPS) // 131072

// ---------------- device scratch ----------------
__device__ float g_h[BSZ * DDIM];                       // fp32 h state
__device__ float g_tmp[BSZ * TMPN];                     // per-step GEMM out
__device__ float g_q1e[(size_t)NROWS * HDIM];           // fp32 posterior emb-side preact
__device__ __nv_bfloat16 g_Ah[BSZ * 768];               // h split [hi|hi|lo] (scan)
__device__ __nv_bfloat16 g_Wcat[TMPN * 768];            // [Wp1;Wq1h;Whh] split (scan)
// MLP weights, hi/lo pairs
__device__ __nv_bfloat16 g_W1hi[256 * 64],  g_W1lo[256 * 64];
__device__ __nv_bfloat16 g_W2hi[256 * 256], g_W2lo[256 * 256];
__device__ __nv_bfloat16 g_W3hi[256 * 256], g_W3lo[256 * 256];

// grid barrier state
__device__ unsigned g_bar_count = 0;
__device__ volatile unsigned g_bar_gen = 0;

// ---------------- split helpers ----------------
__device__ __forceinline__ void split_bf16(float x, __nv_bfloat16& hi, __nv_bfloat16& lo) {
    hi = __float2bfloat16_rn(x);
    lo = __float2bfloat16_rn(x - __bfloat162float(hi));
}

// pack weight fp32 [nrows x K] (row stride srcld) -> bf16 [nrows x 3K] = [Whi|Wlo|Whi] (scan)
__global__ void pack_split_kernel(const float* __restrict__ src, int srcld,
                                  int nrows, int K, __nv_bfloat16* __restrict__ dst)
{
    int idx = blockIdx.x * blockDim.x + threadIdx.x;
    int total = nrows * K;
    if (idx >= total) return;
    int r = idx / K, k = idx - r * K;
    float w = src[(size_t)r * srcld + k];
    __nv_bfloat16 hi, lo; split_bf16(w, hi, lo);
    __nv_bfloat16* d = dst + (size_t)r * (3 * K);
    d[k] = hi; d[K + k] = lo; d[2 * K + k] = hi;
}

// pack weight fp32 -> separate hi / lo bf16 arrays (mlp)
__global__ void pack2_kernel(const float* __restrict__ src, int srcld,
                             int nrows, int K,
                             __nv_bfloat16* __restrict__ dhi,
                             __nv_bfloat16* __restrict__ dlo)
{
    int idx = blockIdx.x * blockDim.x + threadIdx.x;
    if (idx >= nrows * K) return;
    int r = idx / K, k = idx - r * K;
    float w = src[(size_t)r * srcld + k];
    __nv_bfloat16 hi, lo; split_bf16(w, hi, lo);
    dhi[idx] = hi; dlo[idx] = lo;
}

// ---------------- mma helpers ----------------
__device__ __forceinline__ void mma_bf16(float* c, const uint32_t* a, const uint32_t* b) {
    asm volatile(
        "mma.sync.aligned.m16n8k16.row.col.f32.bf16.bf16.f32 "
        "{%0,%1,%2,%3}, {%4,%5,%6,%7}, {%8,%9}, {%0,%1,%2,%3};\n"
        : "+f"(c[0]), "+f"(c[1]), "+f"(c[2]), "+f"(c[3])
        : "r"(a[0]), "r"(a[1]), "r"(a[2]), "r"(a[3]), "r"(b[0]), "r"(b[1]));
}

__device__ __forceinline__ uint32_t smem_u32(const void* p) {
    return (uint32_t)__cvta_generic_to_shared(p);
}
__device__ __forceinline__ void cp16(void* dst, const void* src) {
    asm volatile("cp.async.cg.shared.global [%0], [%1], 16;\n"
                 :: "r"(smem_u32(dst)), "l"(src));
}
__device__ __forceinline__ void cp_commit() { asm volatile("cp.async.commit_group;\n"); }
template <int N>
__device__ __forceinline__ void cp_wait() { asm volatile("cp.async.wait_group %0;\n"::"n"(N)); }

// ================= fused precompute MLP kernel =================
// q1e = (elu(elu(obs@We1^T+be1)@We2^T+be2))@Wq1e^T + bq1
// 2048 blocks x 256 threads, 64 rows/block. Intermediates stay in SMEM.
// 3-term split: acc = Ahi@Whi + Ahi@Wlo + Alo@Whi (fp32 accumulate).
#define MRM 64
#define SA 264     // act row stride (bf16)
#define SW 72      // w tile row stride (bf16)
// smem layout (bytes)
#define MS_AH 0
#define MS_AL (MRM * SA * 2)                 // 33792
#define MS_W  (2 * MRM * SA * 2)             // 67584 ; 4 parts of 256*SW*2=36864
#define MS_WPART (256 * SW * 2)
#define MS_TOTAL (MS_W + 4 * MS_WPART)       // 215040

__device__ __forceinline__ void mma_tiles3(
    const __nv_bfloat16* AH, const __nv_bfloat16* AL,
    const __nv_bfloat16* WH, const __nv_bfloat16* WL,
    int kbase, int wm, int wn, int gid, int tg,
    float (*acc)[8][4])
{
#pragma unroll
    for (int kt = 0; kt < 4; kt++) {
        const int ka = kbase + kt * 16 + tg * 2;
        const int kw = kt * 16 + tg * 2;
        uint32_t ah[2][4], al[2][4];
#pragma unroll
        for (int mf = 0; mf < 2; mf++) {
            const int R = wm * 32 + mf * 16 + gid;
            ah[mf][0] = *(const uint32_t*)(&AH[R * SA + ka]);
            ah[mf][1] = *(const uint32_t*)(&AH[(R + 8) * SA + ka]);
            ah[mf][2] = *(const uint32_t*)(&AH[R * SA + ka + 8]);
            ah[mf][3] = *(const uint32_t*)(&AH[(R + 8) * SA + ka + 8]);
            al[mf][0] = *(const uint32_t*)(&AL[R * SA + ka]);
            al[mf][1] = *(const uint32_t*)(&AL[(R + 8) * SA + ka]);
            al[mf][2] = *(const uint32_t*)(&AL[R * SA + ka + 8]);
            al[mf][3] = *(const uint32_t*)(&AL[(R + 8) * SA + ka + 8]);
        }
#pragma unroll
        for (int nf = 0; nf < 8; nf++) {
            const int C = wn * 64 + nf * 8 + gid;
            uint32_t bh[2], bl[2];
            bh[0] = *(const uint32_t*)(&WH[C * SW + kw]);
            bh[1] = *(const uint32_t*)(&WH[C * SW + kw + 8]);
            bl[0] = *(const uint32_t*)(&WL[C * SW + kw]);
            bl[1] = *(const uint32_t*)(&WL[C * SW + kw + 8]);
#pragma unroll
            for (int mf = 0; mf < 2; mf++) {
                mma_bf16(acc[mf][nf], ah[mf], bh);
                mma_bf16(acc[mf][nf], ah[mf], bl);
                mma_bf16(acc[mf][nf], al[mf], bh);
            }
        }
    }
}

// load one 64-k chunk of a [256 x 256] weight (hi+lo) into a W stage via cp.async
__device__ __forceinline__ void issue_wchunk(
    char* sm, int stage, int tid,
    const __nv_bfloat16* Ghi, const __nv_bfloat16* Glo, int gld, int kofs)
{
    __nv_bfloat16* WH = (__nv_bfloat16*)(sm + MS_W + (stage * 2 + 0) * MS_WPART);
    __nv_bfloat16* WL = (__nv_bfloat16*)(sm + MS_W + (stage * 2 + 1) * MS_WPART);
#pragma unroll
    for (int j = 0; j < 8; j++) {
        int idx = tid + j * 256;           // 0..2047
        int n = idx >> 3, kk = (idx & 7) * 8;
        cp16(&WH[n * SW + kk], &Ghi[(size_t)n * gld + kofs + kk]);
        cp16(&WL[n * SW + kk], &Glo[(size_t)n * gld + kofs + kk]);
    }
    cp_commit();
}

__global__ __launch_bounds__(256, 1) void mlp_kernel(
    const float* __restrict__ obs,
    const float* __restrict__ be1,
    const float* __restrict__ be2,
    const float* __restrict__ bq1,
    float* __restrict__ q1e)
{
    extern __shared__ char sm[];
    __nv_bfloat16* AH = (__nv_bfloat16*)(sm + MS_AH);
    __nv_bfloat16* AL = (__nv_bfloat16*)(sm + MS_AL);

    const int tid = threadIdx.x;
    const int lane = tid & 31;
    const int warp = tid >> 5;
    const int gid = lane >> 2;
    const int tg = lane & 3;
    const int wm = warp & 1;     // 2 M-warps x 32 rows
    const int wn = warp >> 1;    // 4 N-warps x 64 cols
    const size_t row0 = (size_t)blockIdx.x * MRM;

    float acc[2][8][4];

    // ---- stage obs into Act (cols 0..63) split hi/lo ----
    for (int i = tid; i < MRM * OBS; i += 256) {
        int r = i >> 6, c = i & 63;
        float v = obs[(row0 + r) * OBS + c];
        __nv_bfloat16 hi, lo; split_bf16(v, hi, lo);
        AH[r * SA + c] = hi; AL[r * SA + c] = lo;
    }
    // layer1 weights (K=64) into stage 0
    {
        __nv_bfloat16* WH = (__nv_bfloat16*)(sm + MS_W + 0 * MS_WPART);
        __nv_bfloat16* WL = (__nv_bfloat16*)(sm + MS_W + 1 * MS_WPART);
#pragma unroll
        for (int j = 0; j < 8; j++) {
            int idx = tid + j * 256;
            int n = idx >> 3, kk = (idx & 7) * 8;
            cp16(&WH[n * SW + kk], &g_W1hi[n * 64 + kk]);
            cp16(&WL[n * SW + kk], &g_W1lo[n * 64 + kk]);
        }
        cp_commit();
    }
    cp_wait<0>();
    __syncthreads();

    // ---- layer 1: K=64 ----
#pragma unroll
    for (int mf = 0; mf < 2; mf++)
#pragma unroll
        for (int nf = 0; nf < 8; nf++)
#pragma unroll
            for (int q = 0; q < 4; q++) acc[mf][nf][q] = 0.f;
    mma_tiles3(AH, AL,
               (__nv_bfloat16*)(sm + MS_W + 0 * MS_WPART),
               (__nv_bfloat16*)(sm + MS_W + 1 * MS_WPART),
               0, wm, wn, gid, tg, acc);
    __syncthreads();
    // epilogue: bias + ELU -> Act (in place)
#pragma unroll
    for (int mf = 0; mf < 2; mf++)
#pragma unroll
        for (int nf = 0; nf < 8; nf++) {
            const int R = wm * 32 + mf * 16 + gid;
            const int C = wn * 64 + nf * 8 + tg * 2;
            float b0 = be1[C], b1 = be1[C + 1];
            float v0 = acc[mf][nf][0] + b0, v1 = acc[mf][nf][1] + b1;
            float v2 = acc[mf][nf][2] + b0, v3 = acc[mf][nf][3] + b1;
            v0 = v0 > 0.f ? v0 : expm1f(v0);
            v1 = v1 > 0.f ? v1 : expm1f(v1);
            v2 = v2 > 0.f ? v2 : expm1f(v2);
            v3 = v3 > 0.f ? v3 : expm1f(v3);
            __nv_bfloat16 h0, l0, h1, l1, h2, l2, h3, l3;
            split_bf16(v0, h0, l0); split_bf16(v1, h1, l1);
            split_bf16(v2, h2, l2); split_bf16(v3, h3, l3);
            *(__nv_bfloat162*)(&AH[R * SA + C])       = __nv_bfloat162(h0, h1);
            *(__nv_bfloat162*)(&AL[R * SA + C])       = __nv_bfloat162(l0, l1);
            *(__nv_bfloat162*)(&AH[(R + 8) * SA + C]) = __nv_bfloat162(h2, h3);
            *(__nv_bfloat162*)(&AL[(R + 8) * SA + C]) = __nv_bfloat162(l2, l3);
        }
    __syncthreads();

    // ---- layers 2 & 3: K=256 streamed in 4 chunks ----
    for (int layer = 0; layer < 2; layer++) {
        const __nv_bfloat16* Ghi = layer == 0 ? g_W2hi : g_W3hi;
        const __nv_bfloat16* Glo = layer == 0 ? g_W2lo : g_W3lo;
        const float* bias = layer == 0 ? be2 : bq1;

#pragma unroll
        for (int mf = 0; mf < 2; mf++)
#pragma unroll
            for (int nf = 0; nf < 8; nf++)
#pragma unroll
                for (int q = 0; q < 4; q++) acc[mf][nf][q] = 0.f;

        issue_wchunk(sm, 0, tid, Ghi, Glo, 256, 0);
        for (int c = 0; c < 4; c++) {
            if (c + 1 < 4) {
                issue_wchunk(sm, (c + 1) & 1, tid, Ghi, Glo, 256, (c + 1) * 64);
                cp_wait<1>();
            } else {
                cp_wait<0>();
            }
            __syncthreads();
            mma_tiles3(AH, AL,
                       (__nv_bfloat16*)(sm + MS_W + ((c & 1) * 2 + 0) * MS_WPART),
                       (__nv_bfloat16*)(sm + MS_W + ((c & 1) * 2 + 1) * MS_WPART),
                       c * 64, wm, wn, gid, tg, acc);
            __syncthreads();
        }

        if (layer == 0) {
            // ELU epilogue, in-place to Act
#pragma unroll
            for (int mf = 0; mf < 2; mf++)
#pragma unroll
                for (int nf = 0; nf < 8; nf++) {
                    const int R = wm * 32 + mf * 16 + gid;
                    const int C = wn * 64 + nf * 8 + tg * 2;
                    float b0 = bias[C], b1 = bias[C + 1];
                    float v0 = acc[mf][nf][0] + b0, v1 = acc[mf][nf][1] + b1;
                    float v2 = acc[mf][nf][2] + b0, v3 = acc[mf][nf][3] + b1;
                    v0 = v0 > 0.f ? v0 : expm1f(v0);
                    v1 = v1 > 0.f ? v1 : expm1f(v1);
                    v2 = v2 > 0.f ? v2 : expm1f(v2);
                    v3 = v3 > 0.f ? v3 : expm1f(v3);
                    __nv_bfloat16 h0, l0, h1, l1, h2, l2, h3, l3;
                    split_bf16(v0, h0, l0); split_bf16(v1, h1, l1);
                    split_bf16(v2, h2, l2); split_bf16(v3, h3, l3);
                    *(__nv_bfloat162*)(&AH[R * SA + C])       = __nv_bfloat162(h0, h1);
                    *(__nv_bfloat162*)(&AL[R * SA + C])       = __nv_bfloat162(l0, l1);
                    *(__nv_bfloat162*)(&AH[(R + 8) * SA + C]) = __nv_bfloat162(h2, h3);
                    *(__nv_bfloat162*)(&AL[(R + 8) * SA + C]) = __nv_bfloat162(l2, l3);
                }
            __syncthreads();
        } else {
            // final: bias only, fp32 -> global q1e
#pragma unroll
            for (int mf = 0; mf < 2; mf++)
#pragma unroll
                for (int nf = 0; nf < 8; nf++) {
                    const int R = wm * 32 + mf * 16 + gid;
                    const int C = wn * 64 + nf * 8 + tg * 2;
                    float b0 = bias[C], b1 = bias[C + 1];
                    *(float2*)(&q1e[(row0 + R) * 256 + C]) =
                        make_float2(acc[mf][nf][0] + b0, acc[mf][nf][1] + b1);
                    *(float2*)(&q1e[(row0 + R + 8) * 256 + C]) =
                        make_float2(acc[mf][nf][2] + b0, acc[mf][nf][3] + b1);
                }
        }
    }
}

// ================= persistent scan kernel (unchanged from R5) =================
#define NBLK 128
#define WSLICE 80
#define WPAD 776
#define KTILES 48

#define SM_W    0
#define SM_AS   (WSLICE * WPAD * 2)
#define SM_PQ   (SM_AS + 2 * 128 * 24 * 2)
#define SM_ST   (SM_PQ + 2 * 8 * 256 * 4)
#define SM_ZA   (SM_ST + 8 * 128 * 4)
#define SM_TOTAL (SM_ZA + 8 * 40 * 4)

__device__ __forceinline__ float sigmf(float x) { return 1.f / (1.f + expf(-x)); }

__device__ __forceinline__ void grid_sync() {
    __syncthreads();
    if (threadIdx.x == 0) {
        __threadfence();
        unsigned gen = g_bar_gen;
        unsigned arrived = atomicAdd(&g_bar_count, 1u);
        if (arrived == NBLK - 1) {
            g_bar_count = 0;
            __threadfence();
            g_bar_gen = gen + 1;
        } else {
            while (g_bar_gen == gen) { }
        }
        __threadfence();
    }
    __syncthreads();
}

__global__ __launch_bounds__(256, 1) void scan_kernel(
    const float* __restrict__ q1e,
    const float* __restrict__ noise,
    const float* __restrict__ act,
    const float* __restrict__ Wp2, const float* __restrict__ bp2,
    const float* __restrict__ Wq2, const float* __restrict__ bq2,
    const float* __restrict__ bp1,
    const float* __restrict__ Wih, const float* __restrict__ bih,
    const float* __restrict__ bhh,
    float* __restrict__ out)
{
    extern __shared__ char smraw[];
    __nv_bfloat16* Wsm = (__nv_bfloat16*)(smraw + SM_W);
    __nv_bfloat16* As  = (__nv_bfloat16*)(smraw + SM_AS);
    float* PQ = (float*)(smraw + SM_PQ);
    float* ST = (float*)(smraw + SM_ST);
    float* ZA = (float*)(smraw + SM_ZA);

    const int tid = threadIdx.x;
    const int blk = blockIdx.x;
    const int lane = tid & 31;
    const int warp = tid >> 5;
    const int gid = lane >> 2;
    const int tg = lane & 3;
    const int wm = warp & 3;
    const int wn = warp >> 2;
    const int bs = blk >> 4;
    const int cs = blk & 15;
    const int mbase = bs * 128;
    const int nbase = cs * WSLICE;
    const int b0 = blk * 8;

    for (int i = tid; i < WSLICE * 768; i += 256) {
        int r = i / 768, k = i - r * 768;
        Wsm[r * WPAD + k] = g_Wcat[(size_t)(nbase + r) * 768 + k];
    }
    __syncthreads();

    const int lrow = tid >> 1;
    const int kcol = (tid & 1) * 8;

    for (int t = 0; t < TSTEPS; t++) {
        {
            float acc[2][5][4];
#pragma unroll
            for (int i = 0; i < 2; i++)
#pragma unroll
                for (int j = 0; j < 5; j++)
#pragma unroll
                    for (int q = 0; q < 4; q++) acc[i][j][q] = 0.f;

            uint4 av = *(const uint4*)(&g_Ah[(size_t)(mbase + lrow) * 768 + kcol]);
            *(uint4*)(&As[(0 * 128 + lrow) * 24 + kcol]) = av;
            __syncthreads();

            for (int kb = 0; kb < KTILES; kb++) {
                const int cur = kb & 1;
                const bool more = (kb + 1 < KTILES);
                if (more)
                    av = *(const uint4*)(&g_Ah[(size_t)(mbase + lrow) * 768 + (kb + 1) * 16 + kcol]);

                uint32_t af[2][4];
#pragma unroll
                for (int mf = 0; mf < 2; mf++) {
                    const int r = wm * 32 + mf * 16 + gid;
                    const __nv_bfloat16* arow = &As[(cur * 128 + r) * 24];
                    af[mf][0] = *(const uint32_t*)(arow + tg * 2);
                    af[mf][1] = *(const uint32_t*)(arow + 24 * 8 + tg * 2);
                    af[mf][2] = *(const uint32_t*)(arow + tg * 2 + 8);
                    af[mf][3] = *(const uint32_t*)(arow + 24 * 8 + tg * 2 + 8);
                }
                uint32_t bfr[5][2];
#pragma unroll
                for (int nf = 0; nf < 5; nf++) {
                    const int c = wn * 40 + nf * 8 + gid;
                    const __nv_bfloat16* wrow = &Wsm[c * WPAD + kb * 16];
                    bfr[nf][0] = *(const uint32_t*)(wrow + tg * 2);
                    bfr[nf][1] = *(const uint32_t*)(wrow + tg * 2 + 8);
                }
#pragma unroll
                for (int mf = 0; mf < 2; mf++)
#pragma unroll
                    for (int nf = 0; nf < 5; nf++)
                        mma_bf16(acc[mf][nf], af[mf], bfr[nf]);

                if (more)
                    *(uint4*)(&As[((cur ^ 1) * 128 + lrow) * 24 + kcol]) = av;
                __syncthreads();
            }

#pragma unroll
            for (int mf = 0; mf < 2; mf++)
#pragma unroll
                for (int nf = 0; nf < 5; nf++) {
                    const int row = mbase + wm * 32 + mf * 16 + gid;
                    const int col = nbase + wn * 40 + nf * 8 + tg * 2;
                    *(float2*)(&g_tmp[(size_t)row * TMPN + col]) =
                        make_float2(acc[mf][nf][0], acc[mf][nf][1]);
                    *(float2*)(&g_tmp[(size_t)(row + 8) * TMPN + col]) =
                        make_float2(acc[mf][nf][2], acc[mf][nf][3]);
                }
        }
        grid_sync();

        for (int i = tid; i < 8 * 256; i += 256) {
            int r = i >> 8, d = i & 255;
            int b = b0 + r;
            const float* trow = g_tmp + (size_t)b * TMPN;
            float p = trow[d] + bp1[d];
            PQ[(0 * 8 + r) * 256 + d] = p > 0.f ? p : expm1f(p);
            float q = trow[256 + d] + q1e[((size_t)b * TSTEPS + t) * 256 + d];
            PQ[(1 * 8 + r) * 256 + d] = q > 0.f ? q : expm1f(q);
        }
        __syncthreads();

        {
            int j = tid & 127;
            int rbase = tid >> 7;
            bool isq = (j >= 64);
            int jj = isq ? j - 64 : j;
            const float* wrow = (isq ? Wq2 : Wp2) + jj * 256;
            float bb = (isq ? bq2 : bp2)[jj];
            const float* base = PQ + (isq ? 8 * 256 : 0);

            float accm[4] = {0.f, 0.f, 0.f, 0.f};
            for (int k = 0; k < 256; k += 4) {
                float4 w = *(const float4*)(wrow + k);
#pragma unroll
                for (int m = 0; m < 4; m++) {
                    int r = rbase + 2 * m;
                    float4 s = *(const float4*)(base + r * 256 + k);
                    accm[m] += s.x * w.x + s.y * w.y + s.z * w.z + s.w * w.w;
                }
            }
#pragma unroll
            for (int m = 0; m < 4; m++) ST[(rbase + 2 * m) * 128 + j] = accm[m] + bb;
        }
        __syncthreads();

        {
            int r = tid >> 5, s = tid & 31;
            int b = b0 + r;
            float qm = ST[r * 128 + 64 + s];
            float ql = fminf(fmaxf(ST[r * 128 + 96 + s], -7.f), 5.f);
            float qs = expf(ql);
            float eps = noise[((size_t)t * BSZ + b) * SDIM + s];
            ZA[r * 40 + s] = qm + qs * eps;
        }
        if (tid < 8 * ACTD) {
            int r = tid >> 3, j = tid & 7;
            int b = b0 + r;
            ZA[r * 40 + 32 + j] = act[((size_t)b * TSTEPS + t) * ACTD + j];
        }
        __syncthreads();

#pragma unroll 1
        for (int r = 0; r < 8; r++) {
            int d = tid;
            int b = b0 + r;
            float gi[3];
#pragma unroll
            for (int g = 0; g < 3; g++) {
                const float* w = Wih + (size_t)(g * 256 + d) * 40;
                float a = 0.f;
#pragma unroll
                for (int k4 = 0; k4 < 10; k4++) {
                    float4 wv = *(const float4*)(w + 4 * k4);
                    float4 sv = *(const float4*)(&ZA[r * 40 + 4 * k4]);
                    a += sv.x * wv.x + sv.y * wv.y + sv.z * wv.z + sv.w * wv.w;
                }
                gi[g] = a + bih[g * 256 + d];
            }
            const float* trow = g_tmp + (size_t)b * TMPN + 512;
            float ghr = trow[d]        + bhh[d];
            float ghu = trow[256 + d]  + bhh[256 + d];
            float ghn = trow[512 + d]  + bhh[512 + d];
            float rg = sigmf(gi[0] + ghr);
            float u  = sigmf(gi[1] + ghu);
            float nn = tanhf(gi[2] + rg * ghn);
            float hold = g_h[(size_t)b * DDIM + d];
            float hnew = (1.f - u) * nn + u * hold;
            out[((size_t)b * TSTEPS + t) * OUTW + d] = hold;
            g_h[(size_t)b * DDIM + d] = hnew;
            __nv_bfloat16 hi, lo; split_bf16(hnew, hi, lo);
            __nv_bfloat16* arow = g_Ah + (size_t)b * 768;
            arow[d] = hi; arow[256 + d] = hi; arow[512 + d] = lo;
        }

        for (int i = tid; i < 8 * 160; i += 256) {
            int r = i / 160, c = i - r * 160;
            int b = b0 + r;
            float v;
            if (c < 32) {
                v = ZA[r * 40 + c];
            } else {
                v = ST[r * 128 + c - 32];
                if ((c >= 64 && c < 96) || c >= 128) {
                    v = expf(fminf(fmaxf(v, -7.f), 5.f));
                }
            }
            out[((size_t)b * TSTEPS + t) * OUTW + 256 + c] = v;
        }
        grid_sync();
    }
}

// ---------------- host launch ----------------
extern "C" void kernel_launch(void* const* d_in, const int* in_sizes, int n_in,
                              void* d_out, int out_size)
{
    (void)in_sizes; (void)n_in; (void)out_size;
    const float* obs  = (const float*)d_in[0];
    const float* actp = (const float*)d_in[1];
    const float* noi  = (const float*)d_in[2];
    const float* We1  = (const float*)d_in[3];
    const float* be1  = (const float*)d_in[4];
    const float* We2  = (const float*)d_in[5];
    const float* be2  = (const float*)d_in[6];
    const float* Wih  = (const float*)d_in[7];
    const float* Whh  = (const float*)d_in[8];
    const float* bih  = (const float*)d_in[9];
    const float* bhh  = (const float*)d_in[10];
    const float* Wp1  = (const float*)d_in[11];
    const float* bp1  = (const float*)d_in[12];
    const float* Wp2  = (const float*)d_in[13];
    const float* bp2  = (const float*)d_in[14];
    const float* Wq1  = (const float*)d_in[15];
    const float* bq1  = (const float*)d_in[16];
    const float* Wq2  = (const float*)d_in[17];
    const float* bq2  = (const float*)d_in[18];
    float* out = (float*)d_out;

    float *p_h, *p_q1e;
    __nv_bfloat16 *p_Ah, *p_Wcat;
    __nv_bfloat16 *p_W1hi, *p_W1lo, *p_W2hi, *p_W2lo, *p_W3hi, *p_W3lo;
    cudaGetSymbolAddress((void**)&p_h,    g_h);
    cudaGetSymbolAddress((void**)&p_q1e,  g_q1e);
    cudaGetSymbolAddress((void**)&p_Ah,   g_Ah);
    cudaGetSymbolAddress((void**)&p_Wcat, g_Wcat);
    cudaGetSymbolAddress((void**)&p_W1hi, g_W1hi);
    cudaGetSymbolAddress((void**)&p_W1lo, g_W1lo);
    cudaGetSymbolAddress((void**)&p_W2hi, g_W2hi);
    cudaGetSymbolAddress((void**)&p_W2lo, g_W2lo);
    cudaGetSymbolAddress((void**)&p_W3hi, g_W3hi);
    cudaGetSymbolAddress((void**)&p_W3lo, g_W3lo);

    cudaFuncSetAttribute(mlp_kernel,
                         cudaFuncAttributeMaxDynamicSharedMemorySize, MS_TOTAL);
    cudaFuncSetAttribute(scan_kernel,
                         cudaFuncAttributeMaxDynamicSharedMemorySize, SM_TOTAL);

    cudaMemsetAsync(p_h, 0, sizeof(float) * BSZ * DDIM, 0);
    cudaMemsetAsync(p_Ah, 0, sizeof(__nv_bfloat16) * BSZ * 768, 0);

    // ---- pack weights ----
    {
        auto blocks = [](int n) { return (n + 255) / 256; };
        // scan W_cat (triple split layout)
        pack_split_kernel<<<blocks(256 * 256), 256>>>(Wp1, 256, 256, 256, p_Wcat);
        pack_split_kernel<<<blocks(256 * 256), 256>>>(Wq1, 512, 256, 256, p_Wcat + (size_t)256 * 768);
        pack_split_kernel<<<blocks(768 * 256), 256>>>(Whh, 256, 768, 256, p_Wcat + (size_t)512 * 768);
        // mlp weights (hi/lo pairs)
        pack2_kernel<<<blocks(256 * 64),  256>>>(We1, 64,  256, 64,  p_W1hi, p_W1lo);
        pack2_kernel<<<blocks(256 * 256), 256>>>(We2, 256, 256, 256, p_W2hi, p_W2lo);
        pack2_kernel<<<blocks(256 * 256), 256>>>(Wq1 + 256, 512, 256, 256, p_W3hi, p_W3lo);
    }

    // ---- fused precompute: q1e for all (b,t) ----
    mlp_kernel<<<NROWS / MRM, 256, MS_TOTAL>>>(obs, be1, be2, bq1, p_q1e);

    // ---- persistent scan ----
    scan_kernel<<<NBLK, 256, SM_TOTAL>>>(p_q1e, noi, actp,
                                         Wp2, bp2, Wq2, bq2, bp1,
                                         Wih, bih, bhh, out);
}